// round 1
// baseline (speedup 1.0000x reference)
#include <cuda_runtime.h>
#include <cuda_bf16.h>
#include <stdint.h>

#define NU 100000
#define NB 50000
#define NN 150000
#define D  64
#define NE 2400000

// ---------------- scratch (device globals: allocation-free) ----------------
__device__ float g_embA[NN * D];
__device__ float g_embB[NN * D];
__device__ int   g_deg[NN];
__device__ float g_dinv[NN];
__device__ int   g_off[NN + 1];
__device__ int   g_cur[NN];
__device__ int   g_csr_frm[NE];
__device__ float g_csr_norm[NE];

// ---------------- kernels ----------------

__global__ void k_zero_deg() {
    int i = blockIdx.x * blockDim.x + threadIdx.x;
    if (i < NN) g_deg[i] = 0;
}

// emb0 = embedding + concat(user_proj, book_proj); also init embA and acc
__global__ void k_emb0(const float* __restrict__ emb,
                       const float* __restrict__ uf,
                       const float* __restrict__ bnf,
                       const float* __restrict__ bgf,
                       const float* __restrict__ Wu, const float* __restrict__ bu,
                       const float* __restrict__ Wn, const float* __restrict__ bn,
                       const float* __restrict__ Wg, const float* __restrict__ bg,
                       float* __restrict__ out_emb0,
                       float* __restrict__ acc) {
    int node = blockIdx.x * 4 + (threadIdx.x >> 6);
    int d    = threadIdx.x & 63;
    if (node >= NN) return;
    float v = emb[node * D + d];
    if (node < NU) {
        const float* f = uf + node * 16;
        float s = bu[d];
#pragma unroll
        for (int k = 0; k < 16; k++) s += f[k] * Wu[k * D + d];
        v += s;
    } else {
        int b = node - NU;
        float s = bn[d] + bg[d];
        const float* fn = bnf + b * 8;
#pragma unroll
        for (int k = 0; k < 8; k++) s += fn[k] * Wn[k * D + d];
        const float* fg = bgf + b * 32;
#pragma unroll
        for (int k = 0; k < 32; k++) s += fg[k] * Wg[k * D + d];
        v += s;
    }
    int o = node * D + d;
    out_emb0[o] = v;
    g_embA[o]   = v;
    acc[o]      = v;
}

__global__ void k_degree(const int* __restrict__ to) {
    int e = blockIdx.x * blockDim.x + threadIdx.x;
    if (e < NE) atomicAdd(&g_deg[to[e]], 1);
}

__global__ void k_dinv() {
    int i = blockIdx.x * blockDim.x + threadIdx.x;
    if (i < NN) {
        int dgi = g_deg[i];
        g_dinv[i] = (dgi > 0) ? rsqrtf((float)dgi) : 0.0f;
    }
}

// single-block exclusive scan of g_deg -> g_off (and copy to g_cur)
__global__ void k_scan() {
    __shared__ int s[1024];
    __shared__ int carry_s;
    int t = threadIdx.x;
    if (t == 0) carry_s = 0;
    __syncthreads();
    for (int base = 0; base < NN; base += 1024) {
        int i = base + t;
        int v = (i < NN) ? g_deg[i] : 0;
        s[t] = v;
        __syncthreads();
        for (int off = 1; off < 1024; off <<= 1) {
            int y = (t >= off) ? s[t - off] : 0;
            __syncthreads();
            s[t] += y;
            __syncthreads();
        }
        int incl  = s[t];
        int carry = carry_s;
        if (i < NN) {
            int ex = carry + incl - v;
            g_off[i] = ex;
            g_cur[i] = ex;
        }
        __syncthreads();
        if (t == 1023) carry_s = carry + s[1023];
        __syncthreads();
    }
    if (t == 0) g_off[NN] = carry_s;
}

__global__ void k_scatter(const int* __restrict__ frm, const int* __restrict__ to) {
    int e = blockIdx.x * blockDim.x + threadIdx.x;
    if (e < NE) {
        int tt = to[e];
        int ff = frm[e];
        int p  = atomicAdd(&g_cur[tt], 1);
        g_csr_frm[p]  = ff;
        g_csr_norm[p] = g_dinv[ff] * g_dinv[tt];
    }
}

// pull-based propagation: one warp per node, lane handles 2 dims (float2)
__global__ void k_prop(const float* __restrict__ src,
                       float* __restrict__ dst,
                       float* __restrict__ acc,
                       int final_layer) {
    int warp = (blockIdx.x * blockDim.x + threadIdx.x) >> 5;
    int lane = threadIdx.x & 31;
    if (warp >= NN) return;
    int n = warp;
    int s = g_off[n];
    int e = g_off[n + 1];
    float2 a = make_float2(0.0f, 0.0f);
    const float2* src2 = (const float2*)src;
    for (int base = s; base < e; base += 32) {
        int idx = base + lane;
        int f = 0;
        float w = 0.0f;
        if (idx < e) {
            f = g_csr_frm[idx];
            w = g_csr_norm[idx];
        }
        int m = min(32, e - base);
#pragma unroll 4
        for (int j = 0; j < m; j++) {
            int   fj = __shfl_sync(0xffffffffu, f, j);
            float wj = __shfl_sync(0xffffffffu, w, j);
            float2 x = src2[fj * 32 + lane];
            a.x += wj * x.x;
            a.y += wj * x.y;
        }
    }
    int o = n * 32 + lane;
    float2 av = ((const float2*)acc)[o];
    av.x += a.x;
    av.y += a.y;
    if (final_layer) {
        av.x *= 0.25f;
        av.y *= 0.25f;
        ((float2*)acc)[o] = av;
    } else {
        ((float2*)acc)[o] = av;
        ((float2*)dst)[o] = a;
    }
}

// ---------------- launch ----------------
extern "C" void kernel_launch(void* const* d_in, const int* in_sizes, int n_in,
                              void* d_out, int out_size) {
    const int*   ei   = (const int*)d_in[0];
    const int*   frm  = ei;
    const int*   to   = ei + NE;
    const float* emb  = (const float*)d_in[1];
    const float* uf   = (const float*)d_in[2];
    const float* bnf  = (const float*)d_in[3];
    const float* bgf  = (const float*)d_in[4];
    const float* Wu   = (const float*)d_in[5];
    const float* bu   = (const float*)d_in[6];
    const float* Wn   = (const float*)d_in[7];
    const float* bn   = (const float*)d_in[8];
    const float* Wg   = (const float*)d_in[9];
    const float* bg   = (const float*)d_in[10];

    float* out  = (float*)d_out;
    float* out0 = out;              // emb0
    float* acc  = out + NN * D;     // running accumulator -> final output

    float* embA;
    float* embB;
    cudaGetSymbolAddress((void**)&embA, g_embA);
    cudaGetSymbolAddress((void**)&embB, g_embB);

    k_zero_deg<<<(NN + 255) / 256, 256>>>();
    k_emb0<<<(NN + 3) / 4, 256>>>(emb, uf, bnf, bgf, Wu, bu, Wn, bn, Wg, bg, out0, acc);
    k_degree<<<(NE + 255) / 256, 256>>>(to);
    k_dinv<<<(NN + 255) / 256, 256>>>();
    k_scan<<<1, 1024>>>();
    k_scatter<<<(NE + 255) / 256, 256>>>(frm, to);

    // 8 warps/block => 8 nodes per block
    int prop_blocks = (NN * 32 + 255) / 256;
    k_prop<<<prop_blocks, 256>>>(embA, embB, acc, 0);  // layer 1: A -> B
    k_prop<<<prop_blocks, 256>>>(embB, embA, acc, 0);  // layer 2: B -> A
    k_prop<<<prop_blocks, 256>>>(embA, embB, acc, 1);  // layer 3: final, scale by 1/4
}

// round 2
// speedup vs baseline: 1.3941x; 1.3941x over previous
#include <cuda_runtime.h>
#include <cuda_bf16.h>
#include <stdint.h>

#define NU 100000
#define NB 50000
#define NN 150000
#define D  64
#define NE 2400000

#define SCAN_BLK 1024
#define NBLK ((NN + SCAN_BLK - 1) / SCAN_BLK)   // 147

// ---------------- scratch (device globals: allocation-free) ----------------
__device__ float g_embA[NN * D];
__device__ float g_embB[NN * D];
__device__ int   g_deg[NN];
__device__ float g_dinv[NN];
__device__ int   g_off[NN + 1];
__device__ int   g_cur[NN];
__device__ int2  g_csr[NE];          // (frm, norm bits) interleaved
__device__ int   g_partial[NBLK];

// ---------------- kernels ----------------

__global__ void k_zero_deg() {
    int i = blockIdx.x * blockDim.x + threadIdx.x;
    if (i < NN) g_deg[i] = 0;
}

// emb0 = embedding + concat(user_proj, book_proj); writes out0 and acc
__global__ void k_emb0(const float* __restrict__ emb,
                       const float* __restrict__ uf,
                       const float* __restrict__ bnf,
                       const float* __restrict__ bgf,
                       const float* __restrict__ Wu, const float* __restrict__ bu,
                       const float* __restrict__ Wn, const float* __restrict__ bn,
                       const float* __restrict__ Wg, const float* __restrict__ bg,
                       float* __restrict__ out_emb0,
                       float* __restrict__ acc) {
    int node = blockIdx.x * 4 + (threadIdx.x >> 6);
    int d    = threadIdx.x & 63;
    if (node >= NN) return;
    float v = emb[node * D + d];
    if (node < NU) {
        const float* f = uf + node * 16;
        float s = bu[d];
#pragma unroll
        for (int k = 0; k < 16; k++) s += f[k] * Wu[k * D + d];
        v += s;
    } else {
        int b = node - NU;
        float s = bn[d] + bg[d];
        const float* fn = bnf + b * 8;
#pragma unroll
        for (int k = 0; k < 8; k++) s += fn[k] * Wn[k * D + d];
        const float* fg = bgf + b * 32;
#pragma unroll
        for (int k = 0; k < 32; k++) s += fg[k] * Wg[k * D + d];
        v += s;
    }
    int o = node * D + d;
    out_emb0[o] = v;
    acc[o]      = v;
}

__global__ void k_degree(const int* __restrict__ to) {
    int e = blockIdx.x * blockDim.x + threadIdx.x;
    if (e < NE) atomicAdd(&g_deg[to[e]], 1);
}

// phase 1: per-block reduce of deg -> g_partial[b]; also compute dinv
__global__ void k_scan1() {
    __shared__ int s[SCAN_BLK / 32];
    int t = threadIdx.x;
    int i = blockIdx.x * SCAN_BLK + t;
    int v = (i < NN) ? g_deg[i] : 0;
    if (i < NN) g_dinv[i] = (v > 0) ? rsqrtf((float)v) : 0.0f;
    // warp reduce
    int w = v;
#pragma unroll
    for (int o = 16; o > 0; o >>= 1) w += __shfl_down_sync(0xffffffffu, w, o);
    if ((t & 31) == 0) s[t >> 5] = w;
    __syncthreads();
    if (t < SCAN_BLK / 32) {
        int x = s[t];
#pragma unroll
        for (int o = 16; o > 0; o >>= 1) x += __shfl_down_sync(0xffffffffu, x, o);
        if (t == 0) g_partial[blockIdx.x] = x;
    }
}

// phase 2: single block exclusive scan of NBLK partials (NBLK=147 <= 256)
__global__ void k_scan2() {
    __shared__ int s[256];
    int t = threadIdx.x;
    int v = (t < NBLK) ? g_partial[t] : 0;
    s[t] = v;
    __syncthreads();
#pragma unroll
    for (int o = 1; o < 256; o <<= 1) {
        int y = (t >= o) ? s[t - o] : 0;
        __syncthreads();
        s[t] += y;
        __syncthreads();
    }
    if (t < NBLK) g_partial[t] = s[t] - v;   // exclusive
}

// phase 3: per-block exclusive scan + add block offset -> g_off, g_cur
__global__ void k_scan3() {
    __shared__ int s[SCAN_BLK];
    int t = threadIdx.x;
    int i = blockIdx.x * SCAN_BLK + t;
    int v = (i < NN) ? g_deg[i] : 0;
    s[t] = v;
    __syncthreads();
#pragma unroll
    for (int o = 1; o < SCAN_BLK; o <<= 1) {
        int y = (t >= o) ? s[t - o] : 0;
        __syncthreads();
        s[t] += y;
        __syncthreads();
    }
    if (i < NN) {
        int ex = g_partial[blockIdx.x] + s[t] - v;
        g_off[i] = ex;
        g_cur[i] = ex;
    }
    if (i == NN - 1) g_off[NN] = NE;
}

__global__ void k_scatter(const int* __restrict__ frm, const int* __restrict__ to) {
    int e = blockIdx.x * blockDim.x + threadIdx.x;
    if (e < NE) {
        int tt = to[e];
        int ff = frm[e];
        int p  = atomicAdd(&g_cur[tt], 1);
        float w = g_dinv[ff] * g_dinv[tt];
        g_csr[p] = make_int2(ff, __float_as_int(w));
    }
}

// pull-based propagation: 16 lanes per node, each lane handles 4 dims (float4)
__global__ void k_prop(const float4* __restrict__ src4,
                       float4* __restrict__ dst4,
                       float4* __restrict__ acc4,
                       int final_layer) {
    int gid  = (blockIdx.x * blockDim.x + threadIdx.x) >> 4;   // node
    int lane = threadIdx.x & 15;
    if (gid >= NN) return;
    int s = g_off[gid];
    int e = g_off[gid + 1];
    float4 a = make_float4(0.0f, 0.0f, 0.0f, 0.0f);
    for (int base = s; base < e; base += 16) {
        int idx = base + lane;
        int2 fw = make_int2(0, 0);
        if (idx < e) fw = g_csr[idx];
        int m = min(16, e - base);
#pragma unroll 4
        for (int j = 0; j < m; j++) {
            int   fj = __shfl_sync(0xffffffffu, fw.x, j, 16);
            float wj = __int_as_float(__shfl_sync(0xffffffffu, fw.y, j, 16));
            float4 x = src4[fj * 16 + lane];
            a.x += wj * x.x;
            a.y += wj * x.y;
            a.z += wj * x.z;
            a.w += wj * x.w;
        }
    }
    int o = gid * 16 + lane;
    float4 av = acc4[o];
    av.x += a.x; av.y += a.y; av.z += a.z; av.w += a.w;
    if (final_layer) {
        av.x *= 0.25f; av.y *= 0.25f; av.z *= 0.25f; av.w *= 0.25f;
        acc4[o] = av;
    } else {
        acc4[o] = av;
        dst4[o] = a;
    }
}

// ---------------- launch ----------------
extern "C" void kernel_launch(void* const* d_in, const int* in_sizes, int n_in,
                              void* d_out, int out_size) {
    const int*   ei   = (const int*)d_in[0];
    const int*   frm  = ei;
    const int*   to   = ei + NE;
    const float* emb  = (const float*)d_in[1];
    const float* uf   = (const float*)d_in[2];
    const float* bnf  = (const float*)d_in[3];
    const float* bgf  = (const float*)d_in[4];
    const float* Wu   = (const float*)d_in[5];
    const float* bu   = (const float*)d_in[6];
    const float* Wn   = (const float*)d_in[7];
    const float* bn   = (const float*)d_in[8];
    const float* Wg   = (const float*)d_in[9];
    const float* bg   = (const float*)d_in[10];

    float* out  = (float*)d_out;
    float* out0 = out;              // emb0
    float* acc  = out + NN * D;     // running accumulator -> final output

    float* embA;
    float* embB;
    cudaGetSymbolAddress((void**)&embA, g_embA);
    cudaGetSymbolAddress((void**)&embB, g_embB);

    k_zero_deg<<<(NN + 255) / 256, 256>>>();
    k_emb0<<<(NN + 3) / 4, 256>>>(emb, uf, bnf, bgf, Wu, bu, Wn, bn, Wg, bg, out0, acc);
    k_degree<<<(NE + 255) / 256, 256>>>(to);
    k_scan1<<<NBLK, SCAN_BLK>>>();
    k_scan2<<<1, 256>>>();
    k_scan3<<<NBLK, SCAN_BLK>>>();
    k_scatter<<<(NE + 255) / 256, 256>>>(frm, to);

    // 16 threads per node
    int prop_threads = NN * 16;
    int prop_blocks  = (prop_threads + 255) / 256;
    k_prop<<<prop_blocks, 256>>>((const float4*)out0, (float4*)embA, (float4*)acc, 0); // L1: out0 -> A
    k_prop<<<prop_blocks, 256>>>((const float4*)embA, (float4*)embB, (float4*)acc, 0); // L2: A -> B
    k_prop<<<prop_blocks, 256>>>((const float4*)embB, (float4*)embA, (float4*)acc, 1); // L3: final
}

// round 3
// speedup vs baseline: 1.5440x; 1.1075x over previous
#include <cuda_runtime.h>
#include <cuda_fp16.h>
#include <stdint.h>

#define NU 100000
#define NB 50000
#define NN 150000
#define D  64
#define NE 2400000

#define SCAN_BLK 1024
#define NBLK ((NN + SCAN_BLK - 1) / SCAN_BLK)   // 147

// ---------------- scratch (device globals: allocation-free) ----------------
__device__ __half g_h16A[NN * D];    // fp16 layer embeddings (ping)
__device__ __half g_h16B[NN * D];    // fp16 layer embeddings (pong)
__device__ int    g_deg[NN];
__device__ float  g_dinv[NN];
__device__ int    g_off[NN + 1];
__device__ int    g_cur[NN];
__device__ int2   g_csr[NE];         // (frm, norm bits) interleaved
__device__ int    g_partial[NBLK];

// ---------------- kernels ----------------

__global__ void k_zero_deg() {
    int i = blockIdx.x * blockDim.x + threadIdx.x;
    if (i < NN) g_deg[i] = 0;
}

// emb0 = embedding + concat(user_proj, book_proj); writes out0 (fp32), acc (fp32),
// and the fp16 copy used as layer-1 gather source.
__global__ void k_emb0(const float* __restrict__ emb,
                       const float* __restrict__ uf,
                       const float* __restrict__ bnf,
                       const float* __restrict__ bgf,
                       const float* __restrict__ Wu, const float* __restrict__ bu,
                       const float* __restrict__ Wn, const float* __restrict__ bn,
                       const float* __restrict__ Wg, const float* __restrict__ bg,
                       float* __restrict__ out_emb0,
                       float* __restrict__ acc) {
    int node = blockIdx.x * 4 + (threadIdx.x >> 6);
    int d    = threadIdx.x & 63;
    if (node >= NN) return;
    float v = emb[node * D + d];
    if (node < NU) {
        const float* f = uf + node * 16;
        float s = bu[d];
#pragma unroll
        for (int k = 0; k < 16; k++) s += f[k] * Wu[k * D + d];
        v += s;
    } else {
        int b = node - NU;
        float s = bn[d] + bg[d];
        const float* fn = bnf + b * 8;
#pragma unroll
        for (int k = 0; k < 8; k++) s += fn[k] * Wn[k * D + d];
        const float* fg = bgf + b * 32;
#pragma unroll
        for (int k = 0; k < 32; k++) s += fg[k] * Wg[k * D + d];
        v += s;
    }
    int o = node * D + d;
    out_emb0[o] = v;
    acc[o]      = v;
    g_h16A[o]   = __float2half_rn(v);
}

__global__ void k_degree(const int* __restrict__ to) {
    int e = blockIdx.x * blockDim.x + threadIdx.x;
    if (e < NE) atomicAdd(&g_deg[to[e]], 1);
}

// phase 1: per-block reduce of deg -> g_partial[b]; also compute dinv
__global__ void k_scan1() {
    __shared__ int s[SCAN_BLK / 32];
    int t = threadIdx.x;
    int i = blockIdx.x * SCAN_BLK + t;
    int v = (i < NN) ? g_deg[i] : 0;
    if (i < NN) g_dinv[i] = (v > 0) ? rsqrtf((float)v) : 0.0f;
    int w = v;
#pragma unroll
    for (int o = 16; o > 0; o >>= 1) w += __shfl_down_sync(0xffffffffu, w, o);
    if ((t & 31) == 0) s[t >> 5] = w;
    __syncthreads();
    if (t < SCAN_BLK / 32) {
        int x = s[t];
#pragma unroll
        for (int o = 16; o > 0; o >>= 1) x += __shfl_down_sync(0xffffffffu, x, o);
        if (t == 0) g_partial[blockIdx.x] = x;
    }
}

// phase 2: single block exclusive scan of NBLK partials (147 <= 256)
__global__ void k_scan2() {
    __shared__ int s[256];
    int t = threadIdx.x;
    int v = (t < NBLK) ? g_partial[t] : 0;
    s[t] = v;
    __syncthreads();
#pragma unroll
    for (int o = 1; o < 256; o <<= 1) {
        int y = (t >= o) ? s[t - o] : 0;
        __syncthreads();
        s[t] += y;
        __syncthreads();
    }
    if (t < NBLK) g_partial[t] = s[t] - v;
}

// phase 3: per-block exclusive scan + block offset -> g_off, g_cur
__global__ void k_scan3() {
    __shared__ int s[SCAN_BLK];
    int t = threadIdx.x;
    int i = blockIdx.x * SCAN_BLK + t;
    int v = (i < NN) ? g_deg[i] : 0;
    s[t] = v;
    __syncthreads();
#pragma unroll
    for (int o = 1; o < SCAN_BLK; o <<= 1) {
        int y = (t >= o) ? s[t - o] : 0;
        __syncthreads();
        s[t] += y;
        __syncthreads();
    }
    if (i < NN) {
        int ex = g_partial[blockIdx.x] + s[t] - v;
        g_off[i] = ex;
        g_cur[i] = ex;
    }
    if (i == NN - 1) g_off[NN] = NE;
}

__global__ void k_scatter(const int* __restrict__ frm, const int* __restrict__ to) {
    int e = blockIdx.x * blockDim.x + threadIdx.x;
    if (e < NE) {
        int tt = to[e];
        int ff = frm[e];
        int p  = atomicAdd(&g_cur[tt], 1);
        float w = g_dinv[ff] * g_dinv[tt];
        g_csr[p] = make_int2(ff, __float_as_int(w));
    }
}

// pull-based propagation, fp16 gather: 8 lanes per node, each lane loads
// uint4 = 8 halves (16B) of the source row; accumulate in fp32.
__global__ void k_prop(const __half* __restrict__ src,
                       __half* __restrict__ dst,
                       float4* __restrict__ acc,
                       int final_layer) {
    int gid  = (blockIdx.x * blockDim.x + threadIdx.x) >> 3;   // node
    int lane = threadIdx.x & 7;
    if (gid >= NN) return;
    int s = g_off[gid];
    int e = g_off[gid + 1];
    float4 a0 = make_float4(0.f, 0.f, 0.f, 0.f);
    float4 a1 = make_float4(0.f, 0.f, 0.f, 0.f);
    const uint4* src16 = (const uint4*)src;   // 8 halves per uint4, row = 8 uint4s
    for (int base = s; base < e; base += 8) {
        int idx = base + lane;
        int2 fw = (idx < e) ? g_csr[idx] : make_int2(0, 0);
        int m = min(8, e - base);
#pragma unroll 4
        for (int j = 0; j < m; j++) {
            int   fj = __shfl_sync(0xffffffffu, fw.x, j, 8);
            float wj = __int_as_float(__shfl_sync(0xffffffffu, fw.y, j, 8));
            uint4 x  = src16[fj * 8 + lane];
            float2 f0 = __half22float2(*(const __half2*)&x.x);
            float2 f1 = __half22float2(*(const __half2*)&x.y);
            float2 f2 = __half22float2(*(const __half2*)&x.z);
            float2 f3 = __half22float2(*(const __half2*)&x.w);
            a0.x += wj * f0.x;  a0.y += wj * f0.y;
            a0.z += wj * f1.x;  a0.w += wj * f1.y;
            a1.x += wj * f2.x;  a1.y += wj * f2.y;
            a1.z += wj * f3.x;  a1.w += wj * f3.y;
        }
    }
    // acc row has 16 float4s; this lane owns float4s [lane*2, lane*2+1]
    int o = gid * 16 + lane * 2;
    float4 av0 = acc[o];
    float4 av1 = acc[o + 1];
    av0.x += a0.x; av0.y += a0.y; av0.z += a0.z; av0.w += a0.w;
    av1.x += a1.x; av1.y += a1.y; av1.z += a1.z; av1.w += a1.w;
    if (final_layer) {
        av0.x *= 0.25f; av0.y *= 0.25f; av0.z *= 0.25f; av0.w *= 0.25f;
        av1.x *= 0.25f; av1.y *= 0.25f; av1.z *= 0.25f; av1.w *= 0.25f;
        acc[o]     = av0;
        acc[o + 1] = av1;
    } else {
        acc[o]     = av0;
        acc[o + 1] = av1;
        __half2 h0 = __floats2half2_rn(a0.x, a0.y);
        __half2 h1 = __floats2half2_rn(a0.z, a0.w);
        __half2 h2 = __floats2half2_rn(a1.x, a1.y);
        __half2 h3 = __floats2half2_rn(a1.z, a1.w);
        uint4 hx;
        hx.x = *(const unsigned*)&h0;
        hx.y = *(const unsigned*)&h1;
        hx.z = *(const unsigned*)&h2;
        hx.w = *(const unsigned*)&h3;
        ((uint4*)dst)[gid * 8 + lane] = hx;
    }
}

// ---------------- launch ----------------
extern "C" void kernel_launch(void* const* d_in, const int* in_sizes, int n_in,
                              void* d_out, int out_size) {
    const int*   ei   = (const int*)d_in[0];
    const int*   frm  = ei;
    const int*   to   = ei + NE;
    const float* emb  = (const float*)d_in[1];
    const float* uf   = (const float*)d_in[2];
    const float* bnf  = (const float*)d_in[3];
    const float* bgf  = (const float*)d_in[4];
    const float* Wu   = (const float*)d_in[5];
    const float* bu   = (const float*)d_in[6];
    const float* Wn   = (const float*)d_in[7];
    const float* bn   = (const float*)d_in[8];
    const float* Wg   = (const float*)d_in[9];
    const float* bg   = (const float*)d_in[10];

    float* out  = (float*)d_out;
    float* out0 = out;              // emb0 (fp32, exact)
    float* acc  = out + NN * D;     // running accumulator -> final output

    __half* hA;
    __half* hB;
    cudaGetSymbolAddress((void**)&hA, g_h16A);
    cudaGetSymbolAddress((void**)&hB, g_h16B);

    k_zero_deg<<<(NN + 255) / 256, 256>>>();
    k_emb0<<<(NN + 3) / 4, 256>>>(emb, uf, bnf, bgf, Wu, bu, Wn, bn, Wg, bg, out0, acc);
    k_degree<<<(NE + 255) / 256, 256>>>(to);
    k_scan1<<<NBLK, SCAN_BLK>>>();
    k_scan2<<<1, 256>>>();
    k_scan3<<<NBLK, SCAN_BLK>>>();
    k_scatter<<<(NE + 255) / 256, 256>>>(frm, to);

    // 8 threads per node
    int prop_threads = NN * 8;
    int prop_blocks  = (prop_threads + 255) / 256;
    k_prop<<<prop_blocks, 256>>>(hA, hB, (float4*)acc, 0);  // L1: A -> B
    k_prop<<<prop_blocks, 256>>>(hB, hA, (float4*)acc, 0);  // L2: B -> A
    k_prop<<<prop_blocks, 256>>>(hA, hB, (float4*)acc, 1);  // L3: final, /4
}